// round 3
// baseline (speedup 1.0000x reference)
#include <cuda_runtime.h>
#include <math.h>

#define DM   1024
#define NH   16
#define HD   64
#define BB   4
#define SS   2048
#define ROWS (BB*SS)   // 8192

// ---------------- scratch (static device buffers; no allocation) ------------
__device__ float g_q[ROWS*DM];
__device__ float g_k[ROWS*DM];
__device__ float g_v[ROWS*DM];
__device__ float g_beta[ROWS*NH];
__device__ float g_attn[ROWS*DM];
__device__ float g_y[ROWS*DM];

// device-side pointer table so the host never needs cudaGetSymbolAddress
__device__ float* g_ptrs[6];

__global__ void init_ptrs_k()
{
    g_ptrs[0] = g_q;
    g_ptrs[1] = g_k;
    g_ptrs[2] = g_v;
    g_ptrs[3] = g_beta;
    g_ptrs[4] = g_attn;
    g_ptrs[5] = g_y;
}

__device__ __forceinline__ float sigmf(float x){ return 1.0f/(1.0f+__expf(-x)); }
__device__ __forceinline__ float siluf(float x){ return x * sigmf(x); }

// ---------------- SGEMM: C[m][n] = act( sum_k A[m][k] * W[n][k] ) -----------
// 128x128 tile, BK=32, 256 threads, 8x8 per thread. M%128==0, N%128==0, K%32==0.
// Fused Q/K/V variant: grid.z in {0,1,2} selects (Wq->g_q, Wk->g_k, Wv->g_v).
__global__ __launch_bounds__(256) void sgemm_qkv(
    const float* __restrict__ A,
    const float* __restrict__ Wq, const float* __restrict__ Wk,
    const float* __restrict__ Wv, int M, int N, int K)
{
    const float* W = (blockIdx.z == 0) ? Wq : (blockIdx.z == 1) ? Wk : Wv;
    float*       C = g_ptrs[blockIdx.z];

    __shared__ float As[32][132];
    __shared__ float Bs[32][132];
    const int tid  = threadIdx.x;
    const int m0   = blockIdx.y * 128;
    const int n0   = blockIdx.x * 128;
    const int tx   = tid & 15;
    const int ty   = tid >> 4;
    const int lrow = tid >> 3;
    const int lcol = (tid & 7) * 4;

    float acc[8][8];
    #pragma unroll
    for (int i = 0; i < 8; ++i)
        #pragma unroll
        for (int j = 0; j < 8; ++j) acc[i][j] = 0.f;

    for (int k0 = 0; k0 < K; k0 += 32) {
        #pragma unroll
        for (int p = 0; p < 4; ++p) {
            float4 av = *(const float4*)&A[(size_t)(m0 + lrow + 32*p) * K + k0 + lcol];
            As[lcol+0][lrow+32*p] = av.x;
            As[lcol+1][lrow+32*p] = av.y;
            As[lcol+2][lrow+32*p] = av.z;
            As[lcol+3][lrow+32*p] = av.w;
            float4 bv = *(const float4*)&W[(size_t)(n0 + lrow + 32*p) * K + k0 + lcol];
            Bs[lcol+0][lrow+32*p] = bv.x;
            Bs[lcol+1][lrow+32*p] = bv.y;
            Bs[lcol+2][lrow+32*p] = bv.z;
            Bs[lcol+3][lrow+32*p] = bv.w;
        }
        __syncthreads();
        #pragma unroll
        for (int kk = 0; kk < 32; ++kk) {
            float a[8], b[8];
            *(float4*)&a[0] = *(const float4*)&As[kk][ty*8];
            *(float4*)&a[4] = *(const float4*)&As[kk][ty*8+4];
            *(float4*)&b[0] = *(const float4*)&Bs[kk][tx*8];
            *(float4*)&b[4] = *(const float4*)&Bs[kk][tx*8+4];
            #pragma unroll
            for (int i = 0; i < 8; ++i)
                #pragma unroll
                for (int j = 0; j < 8; ++j)
                    acc[i][j] += a[i] * b[j];
        }
        __syncthreads();
    }

    #pragma unroll
    for (int i = 0; i < 8; ++i) {
        const size_t m = (size_t)(m0 + ty*8 + i);
        #pragma unroll
        for (int j4 = 0; j4 < 8; j4 += 4) {
            float4 o;
            o.x = siluf(acc[i][j4+0]); o.y = siluf(acc[i][j4+1]);
            o.z = siluf(acc[i][j4+2]); o.w = siluf(acc[i][j4+3]);
            *(float4*)&C[m * N + n0 + tx*8 + j4] = o;
        }
    }
}

// Plain variant for the output projection: C = A @ W^T (no activation).
__global__ __launch_bounds__(256) void sgemm_out(
    const float* __restrict__ W,
    float* __restrict__ C, int M, int N, int K)
{
    const float* A = g_ptrs[5];   // g_y
    __shared__ float As[32][132];
    __shared__ float Bs[32][132];
    const int tid  = threadIdx.x;
    const int m0   = blockIdx.y * 128;
    const int n0   = blockIdx.x * 128;
    const int tx   = tid & 15;
    const int ty   = tid >> 4;
    const int lrow = tid >> 3;
    const int lcol = (tid & 7) * 4;

    float acc[8][8];
    #pragma unroll
    for (int i = 0; i < 8; ++i)
        #pragma unroll
        for (int j = 0; j < 8; ++j) acc[i][j] = 0.f;

    for (int k0 = 0; k0 < K; k0 += 32) {
        #pragma unroll
        for (int p = 0; p < 4; ++p) {
            float4 av = *(const float4*)&A[(size_t)(m0 + lrow + 32*p) * K + k0 + lcol];
            As[lcol+0][lrow+32*p] = av.x;
            As[lcol+1][lrow+32*p] = av.y;
            As[lcol+2][lrow+32*p] = av.z;
            As[lcol+3][lrow+32*p] = av.w;
            float4 bv = *(const float4*)&W[(size_t)(n0 + lrow + 32*p) * K + k0 + lcol];
            Bs[lcol+0][lrow+32*p] = bv.x;
            Bs[lcol+1][lrow+32*p] = bv.y;
            Bs[lcol+2][lrow+32*p] = bv.z;
            Bs[lcol+3][lrow+32*p] = bv.w;
        }
        __syncthreads();
        #pragma unroll
        for (int kk = 0; kk < 32; ++kk) {
            float a[8], b[8];
            *(float4*)&a[0] = *(const float4*)&As[kk][ty*8];
            *(float4*)&a[4] = *(const float4*)&As[kk][ty*8+4];
            *(float4*)&b[0] = *(const float4*)&Bs[kk][tx*8];
            *(float4*)&b[4] = *(const float4*)&Bs[kk][tx*8+4];
            #pragma unroll
            for (int i = 0; i < 8; ++i)
                #pragma unroll
                for (int j = 0; j < 8; ++j)
                    acc[i][j] += a[i] * b[j];
        }
        __syncthreads();
    }

    #pragma unroll
    for (int i = 0; i < 8; ++i) {
        const size_t m = (size_t)(m0 + ty*8 + i);
        #pragma unroll
        for (int j4 = 0; j4 < 8; j4 += 4) {
            float4 o;
            o.x = acc[i][j4+0]; o.y = acc[i][j4+1];
            o.z = acc[i][j4+2]; o.w = acc[i][j4+3];
            *(float4*)&C[m * N + n0 + tx*8 + j4] = o;
        }
    }
}

// ---------------- beta = sigmoid(x @ Wbeta^T), Wbeta is (16,1024) -----------
__global__ __launch_bounds__(128) void beta_gemv(
    const float* __restrict__ x, const float* __restrict__ Wb)
{
    float* beta = g_ptrs[3];
    const int row = blockIdx.x;
    __shared__ float xs[DM];
    const float4* xr = (const float4*)(x + (size_t)row * DM);
    float4* xs4 = (float4*)xs;
    xs4[threadIdx.x]       = xr[threadIdx.x];
    xs4[threadIdx.x + 128] = xr[threadIdx.x + 128];
    __syncthreads();

    const int j  = threadIdx.x >> 3;   // head 0..15
    const int l8 = threadIdx.x & 7;
    const float* wr = Wb + (size_t)j * DM;
    float s = 0.f;
    for (int i = 0; i < DM/8; ++i) {
        int k = l8 + i*8;
        s += xs[k] * wr[k];
    }
    #pragma unroll
    for (int off = 4; off > 0; off >>= 1)
        s += __shfl_down_sync(0xffffffffu, s, off, 8);
    if (l8 == 0) beta[(size_t)row * NH + j] = sigmf(s);
}

// ---------------- per-head l2 normalize (in place): slot 0 = q, 1 = k -------
__global__ __launch_bounds__(512) void l2norm_k()
{
    float* p = g_ptrs[blockIdx.y];   // 0 -> g_q, 1 -> g_k
    const int row  = blockIdx.x;
    const int w    = threadIdx.x >> 5;
    const int lane = threadIdx.x & 31;
    const size_t base = (size_t)row * DM + w * HD;
    float a = p[base + lane];
    float b = p[base + 32 + lane];
    float ss = a*a + b*b;
    #pragma unroll
    for (int off = 16; off > 0; off >>= 1)
        ss += __shfl_xor_sync(0xffffffffu, ss, off);
    float sc = 1.0f / (sqrtf(ss) + 1e-6f);
    p[base + lane]      = a * sc;
    p[base + 32 + lane] = b * sc;
}

// ---------------- delta-rule recurrence -------------------------------------
// One CTA (64 threads) per (b, n). Thread d owns column M[:,d] in registers;
// smem MT[c][h] mirrors M[h][c] for the row-dot (retrieved) phase.
__global__ __launch_bounds__(64) void delta_rec()
{
    const float* q    = g_ptrs[0];
    const float* k    = g_ptrs[1];
    const float* v    = g_ptrs[2];
    const float* beta = g_ptrs[3];
    float*       out  = g_ptrs[4];

    const int b = blockIdx.x >> 4;
    const int n = blockIdx.x & 15;
    const int d = threadIdx.x;

    __shared__ float MT[64][65];
    __shared__ __align__(16) float sq[64];
    __shared__ __align__(16) float sk[64];

    float Mc[64];
    #pragma unroll
    for (int h = 0; h < 64; ++h) { Mc[h] = 0.f; MT[d][h] = 0.f; }

    const size_t off0  = (size_t)(b * SS) * DM + (size_t)n * HD + d;
    const size_t brow0 = (size_t)(b * SS) * NH + n;

    float pq = q[off0], pk = k[off0], pv = v[off0];
    float pb = beta[brow0];

    for (int t = 0; t < SS; ++t) {
        sq[d] = pq; sk[d] = pk;
        const float vv = pv, bt = pb;
        __syncthreads();

        if (t + 1 < SS) {
            const size_t o = off0 + (size_t)(t + 1) * DM;
            pq = q[o]; pk = k[o]; pv = v[o];
            pb = beta[brow0 + (size_t)(t + 1) * NH];
        }

        const float4* sk4 = (const float4*)sk;
        const float4* sq4 = (const float4*)sq;

        // retrieved[h=d] = sum_c M[d][c] * k[c] = sum_c MT[c][d] * k[c]
        float r0 = 0.f, r1 = 0.f, r2 = 0.f, r3 = 0.f;
        #pragma unroll
        for (int j = 0; j < 16; ++j) {
            float4 kv = sk4[j];
            r0 += MT[4*j+0][d] * kv.x;
            r1 += MT[4*j+1][d] * kv.y;
            r2 += MT[4*j+2][d] * kv.z;
            r3 += MT[4*j+3][d] * kv.w;
        }
        const float bdelta = bt * (vv - ((r0 + r1) + (r2 + r3)));

        // out[d] = sum_h q[h] * M[h][d]  (pre-update M, register column)
        float o0 = 0.f, o1 = 0.f, o2 = 0.f, o3 = 0.f;
        #pragma unroll
        for (int h = 0; h < 16; ++h) {
            float4 qv = sq4[h];
            o0 += qv.x * Mc[4*h+0];
            o1 += qv.y * Mc[4*h+1];
            o2 += qv.z * Mc[4*h+2];
            o3 += qv.w * Mc[4*h+3];
        }
        out[off0 + (size_t)t * DM] = (o0 + o1) + (o2 + o3);

        __syncthreads();   // all MT reads done before updates land

        #pragma unroll
        for (int h4 = 0; h4 < 16; ++h4) {
            float4 kv = sk4[h4];
            Mc[4*h4+0] += bdelta * kv.x; MT[d][4*h4+0] = Mc[4*h4+0];
            Mc[4*h4+1] += bdelta * kv.y; MT[d][4*h4+1] = Mc[4*h4+1];
            Mc[4*h4+2] += bdelta * kv.z; MT[d][4*h4+2] = Mc[4*h4+2];
            Mc[4*h4+3] += bdelta * kv.w; MT[d][4*h4+3] = Mc[4*h4+3];
        }
        __syncthreads();   // updates visible before next step's reads
    }
}

// ---------------- RMSNorm: y = attn / sqrt(mean(attn^2)+eps) * w ------------
__global__ __launch_bounds__(256) void rmsnorm_k(const float* __restrict__ w)
{
    const float* x = g_ptrs[4];   // g_attn
    float*       y = g_ptrs[5];   // g_y
    const int row = blockIdx.x;
    const float4* xr = (const float4*)(x + (size_t)row * DM);
    float4 xv = xr[threadIdx.x];
    float ss = xv.x*xv.x + xv.y*xv.y + xv.z*xv.z + xv.w*xv.w;

    __shared__ float red[8];
    #pragma unroll
    for (int off = 16; off > 0; off >>= 1)
        ss += __shfl_xor_sync(0xffffffffu, ss, off);
    if ((threadIdx.x & 31) == 0) red[threadIdx.x >> 5] = ss;
    __syncthreads();
    float total = 0.f;
    #pragma unroll
    for (int i = 0; i < 8; ++i) total += red[i];

    const float inv = rsqrtf(total * (1.0f/DM) + 1e-6f);
    const float4* wr = (const float4*)w;
    float4 wv = wr[threadIdx.x];
    float4 o;
    o.x = xv.x * inv * wv.x;
    o.y = xv.y * inv * wv.y;
    o.z = xv.z * inv * wv.z;
    o.w = xv.w * inv * wv.w;
    ((float4*)(y + (size_t)row * DM))[threadIdx.x] = o;
}

// ---------------- launcher ---------------------------------------------------
extern "C" void kernel_launch(void* const* d_in, const int* in_sizes, int n_in,
                              void* d_out, int out_size)
{
    const float* x   = (const float*)d_in[0];
    const float* Wq  = (const float*)d_in[1];
    const float* Wk  = (const float*)d_in[2];
    const float* Wv  = (const float*)d_in[3];
    const float* Wo  = (const float*)d_in[4];
    const float* Wb  = (const float*)d_in[5];
    const float* rw  = (const float*)d_in[6];
    float* out = (float*)d_out;

    init_ptrs_k<<<1, 1>>>();

    dim3 gqkv(DM/128, ROWS/128, 3);   // (8, 64, 3)
    sgemm_qkv<<<gqkv, 256>>>(x, Wq, Wk, Wv, ROWS, DM, DM);
    beta_gemv<<<ROWS, 128>>>(x, Wb);

    dim3 gnorm(ROWS, 2);
    l2norm_k<<<gnorm, 512>>>();

    delta_rec<<<BB*NH, 64>>>();

    rmsnorm_k<<<ROWS, 256>>>(rw);

    dim3 go(DM/128, ROWS/128);        // (8, 64)
    sgemm_out<<<go, 256>>>(Wo, out, ROWS, DM, DM);
}

// round 4
// speedup vs baseline: 1.0174x; 1.0174x over previous
#include <cuda_runtime.h>
#include <math.h>
#include <stdint.h>

#define DM   1024
#define NH   16
#define HD   64
#define BB   4
#define SS   2048
#define ROWS (BB*SS)   // 8192

// ---------------- scratch (static device buffers; no allocation) ------------
__device__ float g_q[ROWS*DM];
__device__ float g_k[ROWS*DM];
__device__ float g_v[ROWS*DM];
__device__ float g_beta[ROWS*NH];
__device__ float g_attn[ROWS*DM];
__device__ float g_y[ROWS*DM];

__device__ float* g_ptrs[6];

__global__ void init_ptrs_k()
{
    g_ptrs[0] = g_q;
    g_ptrs[1] = g_k;
    g_ptrs[2] = g_v;
    g_ptrs[3] = g_beta;
    g_ptrs[4] = g_attn;
    g_ptrs[5] = g_y;
}

__device__ __forceinline__ float sigmf(float x){ return 1.0f/(1.0f+__expf(-x)); }
__device__ __forceinline__ float siluf(float x){ return x * sigmf(x); }

// ---------------- tf32 helpers ----------------------------------------------
__device__ __forceinline__ uint32_t f2tf32(float x)
{
    uint32_t r;
    asm("cvt.rna.tf32.f32 %0, %1;" : "=r"(r) : "f"(x));
    return r;
}

__device__ __forceinline__ void mma_tf32(float (&d)[4],
    uint32_t a0, uint32_t a1, uint32_t a2, uint32_t a3,
    uint32_t b0, uint32_t b1)
{
    asm volatile(
        "mma.sync.aligned.m16n8k8.row.col.f32.tf32.tf32.f32 "
        "{%0,%1,%2,%3}, {%4,%5,%6,%7}, {%8,%9}, {%0,%1,%2,%3};"
        : "+f"(d[0]), "+f"(d[1]), "+f"(d[2]), "+f"(d[3])
        : "r"(a0), "r"(a1), "r"(a2), "r"(a3), "r"(b0), "r"(b1));
}

// ---------------- 3xTF32 GEMM core: C = act( A @ W^T ) -----------------------
// BM=128, BN=128, BK=16, 256 threads (8 warps), warp tile 32x64.
// A: [M,K] row-major fp32; W: [N,K] row-major fp32; C: [M,N].
// Split x = hi + lo (tf32 each); acc += hi*hi + hi*lo + lo*hi  (~fp32 accuracy)
template<int ACT>
__device__ __forceinline__ void gemm3t_core(
    const float* __restrict__ A, const float* __restrict__ W,
    float* __restrict__ C, int M, int N, int K)
{
    __shared__ uint32_t As_hi[16][136];
    __shared__ uint32_t As_lo[16][136];
    __shared__ uint32_t Ws_hi[16][136];
    __shared__ uint32_t Ws_lo[16][136];

    const int tid  = threadIdx.x;
    const int lane = tid & 31;
    const int wid  = tid >> 5;
    const int m0   = blockIdx.y * 128;
    const int n0   = blockIdx.x * 128;

    const int m0w = (wid >> 1) * 32;   // warp M offset (4 warps over M)
    const int n0w = (wid & 1)  * 64;   // warp N offset (2 warps over N)

    // global loaders: each thread owns one row-half: row = tid>>1, 8 k-floats
    const int grow = tid >> 1;            // 0..127
    const int gk   = (tid & 1) * 8;       // 0 or 8

    float acc[2][8][4];
    #pragma unroll
    for (int i = 0; i < 2; ++i)
        #pragma unroll
        for (int j = 0; j < 8; ++j)
            #pragma unroll
            for (int r = 0; r < 4; ++r) acc[i][j][r] = 0.f;

    // prefetch tile 0
    float4 pa0, pa1, pb0, pb1;
    {
        const float* ap = &A[(size_t)(m0 + grow) * K + gk];
        const float* bp = &W[(size_t)(n0 + grow) * K + gk];
        pa0 = *(const float4*)(ap);
        pa1 = *(const float4*)(ap + 4);
        pb0 = *(const float4*)(bp);
        pb1 = *(const float4*)(bp + 4);
    }

    for (int k0 = 0; k0 < K; k0 += 16) {
        // ---- store current tile (split hi/lo) ----
        {
            float av[8] = {pa0.x,pa0.y,pa0.z,pa0.w, pa1.x,pa1.y,pa1.z,pa1.w};
            float bv[8] = {pb0.x,pb0.y,pb0.z,pb0.w, pb1.x,pb1.y,pb1.z,pb1.w};
            #pragma unroll
            for (int j = 0; j < 8; ++j) {
                uint32_t ah = f2tf32(av[j]);
                uint32_t al = f2tf32(av[j] - __uint_as_float(ah));
                As_hi[gk + j][grow] = ah;
                As_lo[gk + j][grow] = al;
                uint32_t bh = f2tf32(bv[j]);
                uint32_t bl = f2tf32(bv[j] - __uint_as_float(bh));
                Ws_hi[gk + j][grow] = bh;
                Ws_lo[gk + j][grow] = bl;
            }
        }
        __syncthreads();

        // ---- prefetch next tile ----
        if (k0 + 16 < K) {
            const float* ap = &A[(size_t)(m0 + grow) * K + k0 + 16 + gk];
            const float* bp = &W[(size_t)(n0 + grow) * K + k0 + 16 + gk];
            pa0 = *(const float4*)(ap);
            pa1 = *(const float4*)(ap + 4);
            pb0 = *(const float4*)(bp);
            pb1 = *(const float4*)(bp + 4);
        }

        // ---- compute: 2 chunks of k=8 ----
        const int r = lane >> 2;
        const int q = lane & 3;
        #pragma unroll
        for (int c = 0; c < 2; ++c) {
            const int kc = c * 8;
            uint32_t ah[2][4], al[2][4];
            #pragma unroll
            for (int i = 0; i < 2; ++i) {
                const int mb = m0w + i * 16;
                ah[i][0] = As_hi[kc + q    ][mb + r    ];
                ah[i][1] = As_hi[kc + q    ][mb + r + 8];
                ah[i][2] = As_hi[kc + q + 4][mb + r    ];
                ah[i][3] = As_hi[kc + q + 4][mb + r + 8];
                al[i][0] = As_lo[kc + q    ][mb + r    ];
                al[i][1] = As_lo[kc + q    ][mb + r + 8];
                al[i][2] = As_lo[kc + q + 4][mb + r    ];
                al[i][3] = As_lo[kc + q + 4][mb + r + 8];
            }
            #pragma unroll
            for (int j = 0; j < 8; ++j) {
                const int nb = n0w + j * 8 + r;
                uint32_t bh0 = Ws_hi[kc + q    ][nb];
                uint32_t bh1 = Ws_hi[kc + q + 4][nb];
                uint32_t bl0 = Ws_lo[kc + q    ][nb];
                uint32_t bl1 = Ws_lo[kc + q + 4][nb];
                #pragma unroll
                for (int i = 0; i < 2; ++i) {
                    mma_tf32(acc[i][j], ah[i][0], ah[i][1], ah[i][2], ah[i][3], bh0, bh1);
                    mma_tf32(acc[i][j], ah[i][0], ah[i][1], ah[i][2], ah[i][3], bl0, bl1);
                    mma_tf32(acc[i][j], al[i][0], al[i][1], al[i][2], al[i][3], bh0, bh1);
                }
            }
        }
        __syncthreads();
    }

    // ---- epilogue ----
    const int r = lane >> 2;
    const int q = lane & 3;
    #pragma unroll
    for (int i = 0; i < 2; ++i) {
        #pragma unroll
        for (int j = 0; j < 8; ++j) {
            const int row0 = m0 + m0w + i * 16 + r;
            const int col  = n0 + n0w + j * 8 + q * 2;
            float2 v0, v1;
            v0.x = acc[i][j][0]; v0.y = acc[i][j][1];
            v1.x = acc[i][j][2]; v1.y = acc[i][j][3];
            if (ACT == 1) {
                v0.x = siluf(v0.x); v0.y = siluf(v0.y);
                v1.x = siluf(v1.x); v1.y = siluf(v1.y);
            }
            *(float2*)&C[(size_t)row0       * N + col] = v0;
            *(float2*)&C[(size_t)(row0 + 8) * N + col] = v1;
        }
    }
}

// Fused Q/K/V projection: grid.z selects weight + scratch output, SiLU epilogue
__global__ __launch_bounds__(256) void gemm_qkv(
    const float* __restrict__ A,
    const float* __restrict__ Wq, const float* __restrict__ Wk,
    const float* __restrict__ Wv, int M, int N, int K)
{
    const float* W = (blockIdx.z == 0) ? Wq : (blockIdx.z == 1) ? Wk : Wv;
    float*       C = g_ptrs[blockIdx.z];
    gemm3t_core<1>(A, W, C, M, N, K);
}

// Output projection: A = g_y (scratch), no activation
__global__ __launch_bounds__(256) void gemm_out(
    const float* __restrict__ W, float* __restrict__ C, int M, int N, int K)
{
    const float* A = g_ptrs[5];
    gemm3t_core<0>(A, W, C, M, N, K);
}

// ---------------- beta = sigmoid(x @ Wbeta^T), Wbeta is (16,1024) -----------
__global__ __launch_bounds__(128) void beta_gemv(
    const float* __restrict__ x, const float* __restrict__ Wb)
{
    float* beta = g_ptrs[3];
    const int row = blockIdx.x;
    __shared__ float xs[DM];
    const float4* xr = (const float4*)(x + (size_t)row * DM);
    float4* xs4 = (float4*)xs;
    xs4[threadIdx.x]       = xr[threadIdx.x];
    xs4[threadIdx.x + 128] = xr[threadIdx.x + 128];
    __syncthreads();

    const int j  = threadIdx.x >> 3;   // head 0..15
    const int l8 = threadIdx.x & 7;
    const float* wr = Wb + (size_t)j * DM;
    float s = 0.f;
    for (int i = 0; i < DM/8; ++i) {
        int k = l8 + i*8;
        s += xs[k] * wr[k];
    }
    #pragma unroll
    for (int off = 4; off > 0; off >>= 1)
        s += __shfl_down_sync(0xffffffffu, s, off, 8);
    if (l8 == 0) beta[(size_t)row * NH + j] = sigmf(s);
}

// ---------------- per-head l2 normalize (in place): slot 0 = q, 1 = k -------
__global__ __launch_bounds__(512) void l2norm_k()
{
    float* p = g_ptrs[blockIdx.y];   // 0 -> g_q, 1 -> g_k
    const int row  = blockIdx.x;
    const int w    = threadIdx.x >> 5;
    const int lane = threadIdx.x & 31;
    const size_t base = (size_t)row * DM + w * HD;
    float a = p[base + lane];
    float b = p[base + 32 + lane];
    float ss = a*a + b*b;
    #pragma unroll
    for (int off = 16; off > 0; off >>= 1)
        ss += __shfl_xor_sync(0xffffffffu, ss, off);
    float sc = 1.0f / (sqrtf(ss) + 1e-6f);
    p[base + lane]      = a * sc;
    p[base + 32 + lane] = b * sc;
}

// ---------------- delta-rule recurrence -------------------------------------
__global__ __launch_bounds__(64) void delta_rec()
{
    const float* q    = g_ptrs[0];
    const float* k    = g_ptrs[1];
    const float* v    = g_ptrs[2];
    const float* beta = g_ptrs[3];
    float*       out  = g_ptrs[4];

    const int b = blockIdx.x >> 4;
    const int n = blockIdx.x & 15;
    const int d = threadIdx.x;

    __shared__ float MT[64][65];
    __shared__ __align__(16) float sq[64];
    __shared__ __align__(16) float sk[64];

    float Mc[64];
    #pragma unroll
    for (int h = 0; h < 64; ++h) { Mc[h] = 0.f; MT[d][h] = 0.f; }

    const size_t off0  = (size_t)(b * SS) * DM + (size_t)n * HD + d;
    const size_t brow0 = (size_t)(b * SS) * NH + n;

    float pq = q[off0], pk = k[off0], pv = v[off0];
    float pb = beta[brow0];

    for (int t = 0; t < SS; ++t) {
        sq[d] = pq; sk[d] = pk;
        const float vv = pv, bt = pb;
        __syncthreads();

        if (t + 1 < SS) {
            const size_t o = off0 + (size_t)(t + 1) * DM;
            pq = q[o]; pk = k[o]; pv = v[o];
            pb = beta[brow0 + (size_t)(t + 1) * NH];
        }

        const float4* sk4 = (const float4*)sk;
        const float4* sq4 = (const float4*)sq;

        float r0 = 0.f, r1 = 0.f, r2 = 0.f, r3 = 0.f;
        #pragma unroll
        for (int j = 0; j < 16; ++j) {
            float4 kv = sk4[j];
            r0 += MT[4*j+0][d] * kv.x;
            r1 += MT[4*j+1][d] * kv.y;
            r2 += MT[4*j+2][d] * kv.z;
            r3 += MT[4*j+3][d] * kv.w;
        }
        const float bdelta = bt * (vv - ((r0 + r1) + (r2 + r3)));

        float o0 = 0.f, o1 = 0.f, o2 = 0.f, o3 = 0.f;
        #pragma unroll
        for (int h = 0; h < 16; ++h) {
            float4 qv = sq4[h];
            o0 += qv.x * Mc[4*h+0];
            o1 += qv.y * Mc[4*h+1];
            o2 += qv.z * Mc[4*h+2];
            o3 += qv.w * Mc[4*h+3];
        }
        out[off0 + (size_t)t * DM] = (o0 + o1) + (o2 + o3);

        __syncthreads();

        #pragma unroll
        for (int h4 = 0; h4 < 16; ++h4) {
            float4 kv = sk4[h4];
            Mc[4*h4+0] += bdelta * kv.x; MT[d][4*h4+0] = Mc[4*h4+0];
            Mc[4*h4+1] += bdelta * kv.y; MT[d][4*h4+1] = Mc[4*h4+1];
            Mc[4*h4+2] += bdelta * kv.z; MT[d][4*h4+2] = Mc[4*h4+2];
            Mc[4*h4+3] += bdelta * kv.w; MT[d][4*h4+3] = Mc[4*h4+3];
        }
        __syncthreads();
    }
}

// ---------------- RMSNorm: y = attn / sqrt(mean(attn^2)+eps) * w ------------
__global__ __launch_bounds__(256) void rmsnorm_k(const float* __restrict__ w)
{
    const float* x = g_ptrs[4];   // g_attn
    float*       y = g_ptrs[5];   // g_y
    const int row = blockIdx.x;
    const float4* xr = (const float4*)(x + (size_t)row * DM);
    float4 xv = xr[threadIdx.x];
    float ss = xv.x*xv.x + xv.y*xv.y + xv.z*xv.z + xv.w*xv.w;

    __shared__ float red[8];
    #pragma unroll
    for (int off = 16; off > 0; off >>= 1)
        ss += __shfl_xor_sync(0xffffffffu, ss, off);
    if ((threadIdx.x & 31) == 0) red[threadIdx.x >> 5] = ss;
    __syncthreads();
    float total = 0.f;
    #pragma unroll
    for (int i = 0; i < 8; ++i) total += red[i];

    const float inv = rsqrtf(total * (1.0f/DM) + 1e-6f);
    const float4* wr = (const float4*)w;
    float4 wv = wr[threadIdx.x];
    float4 o;
    o.x = xv.x * inv * wv.x;
    o.y = xv.y * inv * wv.y;
    o.z = xv.z * inv * wv.z;
    o.w = xv.w * inv * wv.w;
    ((float4*)(y + (size_t)row * DM))[threadIdx.x] = o;
}

// ---------------- launcher ---------------------------------------------------
extern "C" void kernel_launch(void* const* d_in, const int* in_sizes, int n_in,
                              void* d_out, int out_size)
{
    const float* x   = (const float*)d_in[0];
    const float* Wq  = (const float*)d_in[1];
    const float* Wk  = (const float*)d_in[2];
    const float* Wv  = (const float*)d_in[3];
    const float* Wo  = (const float*)d_in[4];
    const float* Wb  = (const float*)d_in[5];
    const float* rw  = (const float*)d_in[6];
    float* out = (float*)d_out;

    init_ptrs_k<<<1, 1>>>();

    dim3 gqkv(DM/128, ROWS/128, 3);   // (8, 64, 3)
    gemm_qkv<<<gqkv, 256>>>(x, Wq, Wk, Wv, ROWS, DM, DM);
    beta_gemv<<<ROWS, 128>>>(x, Wb);

    dim3 gnorm(ROWS, 2);
    l2norm_k<<<gnorm, 512>>>();

    delta_rec<<<BB*NH, 64>>>();

    rmsnorm_k<<<ROWS, 256>>>(rw);

    dim3 go(DM/128, ROWS/128);        // (8, 64)
    gemm_out<<<go, 256>>>(Wo, out, ROWS, DM, DM);
}

// round 6
// speedup vs baseline: 1.4492x; 1.4245x over previous
#include <cuda_runtime.h>
#include <math.h>
#include <stdint.h>

#define DM   1024
#define NH   16
#define HD   64
#define BB   4
#define SS   2048
#define ROWS (BB*SS)   // 8192
#define CHUNK 64
#define NCH  (SS/CHUNK)       // 32 chunks per chain
#define NCI  (BB*NH*NCH)      // 2048 chunk instances
#define P65  65

// ---------------- scratch (static device buffers; no allocation) ------------
__device__ float g_q[ROWS*DM];
__device__ float g_k[ROWS*DM];
__device__ float g_v[ROWS*DM];
__device__ float g_beta[ROWS*NH];
__device__ float g_attn[ROWS*DM];
__device__ float g_y[ROWS*DM];

// chunked delta-rule scratch
__device__ float g_A [NCI*4096];   // K K^T per chunk
__device__ float g_KV[NCI*4096];   // K V^T per chunk
__device__ float g_U [NCI*4096];   // pseudo-values per chunk
__device__ float g_M0[NCI*4096];   // state checkpoint at chunk start

__device__ float* g_ptrs[6];

__global__ void init_ptrs_k()
{
    g_ptrs[0] = g_q;
    g_ptrs[1] = g_k;
    g_ptrs[2] = g_v;
    g_ptrs[3] = g_beta;
    g_ptrs[4] = g_attn;
    g_ptrs[5] = g_y;
}

__device__ __forceinline__ float sigmf(float x){ return 1.0f/(1.0f+__expf(-x)); }
__device__ __forceinline__ float siluf(float x){ return x * sigmf(x); }

__device__ __forceinline__ void zero44(float (&acc)[4][4])
{
    #pragma unroll
    for (int i = 0; i < 4; ++i)
        #pragma unroll
        for (int j = 0; j < 4; ++j)
            acc[i][j] = 0.f;
}

// ---------------- tf32 helpers ----------------------------------------------
__device__ __forceinline__ uint32_t f2tf32(float x)
{
    uint32_t r;
    asm("cvt.rna.tf32.f32 %0, %1;" : "=r"(r) : "f"(x));
    return r;
}

__device__ __forceinline__ void mma_tf32(float (&d)[4],
    uint32_t a0, uint32_t a1, uint32_t a2, uint32_t a3,
    uint32_t b0, uint32_t b1)
{
    asm volatile(
        "mma.sync.aligned.m16n8k8.row.col.f32.tf32.tf32.f32 "
        "{%0,%1,%2,%3}, {%4,%5,%6,%7}, {%8,%9}, {%0,%1,%2,%3};"
        : "+f"(d[0]), "+f"(d[1]), "+f"(d[2]), "+f"(d[3])
        : "r"(a0), "r"(a1), "r"(a2), "r"(a3), "r"(b0), "r"(b1));
}

// ---------------- 3xTF32 GEMM core: C = act( A @ W^T ) -----------------------
template<int ACT>
__device__ __forceinline__ void gemm3t_core(
    const float* __restrict__ A, const float* __restrict__ W,
    float* __restrict__ C, int M, int N, int K)
{
    __shared__ uint32_t As_hi[16][136];
    __shared__ uint32_t As_lo[16][136];
    __shared__ uint32_t Ws_hi[16][136];
    __shared__ uint32_t Ws_lo[16][136];

    const int tid  = threadIdx.x;
    const int lane = tid & 31;
    const int wid  = tid >> 5;
    const int m0   = blockIdx.y * 128;
    const int n0   = blockIdx.x * 128;

    const int m0w = (wid >> 1) * 32;
    const int n0w = (wid & 1)  * 64;

    const int grow = tid >> 1;
    const int gk   = (tid & 1) * 8;

    float acc[2][8][4];
    #pragma unroll
    for (int i = 0; i < 2; ++i)
        #pragma unroll
        for (int j = 0; j < 8; ++j)
            #pragma unroll
            for (int r = 0; r < 4; ++r) acc[i][j][r] = 0.f;

    float4 pa0, pa1, pb0, pb1;
    {
        const float* ap = &A[(size_t)(m0 + grow) * K + gk];
        const float* bp = &W[(size_t)(n0 + grow) * K + gk];
        pa0 = *(const float4*)(ap);
        pa1 = *(const float4*)(ap + 4);
        pb0 = *(const float4*)(bp);
        pb1 = *(const float4*)(bp + 4);
    }

    for (int k0 = 0; k0 < K; k0 += 16) {
        {
            float av[8] = {pa0.x,pa0.y,pa0.z,pa0.w, pa1.x,pa1.y,pa1.z,pa1.w};
            float bv[8] = {pb0.x,pb0.y,pb0.z,pb0.w, pb1.x,pb1.y,pb1.z,pb1.w};
            #pragma unroll
            for (int j = 0; j < 8; ++j) {
                uint32_t ah = f2tf32(av[j]);
                uint32_t al = f2tf32(av[j] - __uint_as_float(ah));
                As_hi[gk + j][grow] = ah;
                As_lo[gk + j][grow] = al;
                uint32_t bh = f2tf32(bv[j]);
                uint32_t bl = f2tf32(bv[j] - __uint_as_float(bh));
                Ws_hi[gk + j][grow] = bh;
                Ws_lo[gk + j][grow] = bl;
            }
        }
        __syncthreads();

        if (k0 + 16 < K) {
            const float* ap = &A[(size_t)(m0 + grow) * K + k0 + 16 + gk];
            const float* bp = &W[(size_t)(n0 + grow) * K + k0 + 16 + gk];
            pa0 = *(const float4*)(ap);
            pa1 = *(const float4*)(ap + 4);
            pb0 = *(const float4*)(bp);
            pb1 = *(const float4*)(bp + 4);
        }

        const int r = lane >> 2;
        const int q = lane & 3;
        #pragma unroll
        for (int c = 0; c < 2; ++c) {
            const int kc = c * 8;
            uint32_t ah[2][4], al[2][4];
            #pragma unroll
            for (int i = 0; i < 2; ++i) {
                const int mb = m0w + i * 16;
                ah[i][0] = As_hi[kc + q    ][mb + r    ];
                ah[i][1] = As_hi[kc + q    ][mb + r + 8];
                ah[i][2] = As_hi[kc + q + 4][mb + r    ];
                ah[i][3] = As_hi[kc + q + 4][mb + r + 8];
                al[i][0] = As_lo[kc + q    ][mb + r    ];
                al[i][1] = As_lo[kc + q    ][mb + r + 8];
                al[i][2] = As_lo[kc + q + 4][mb + r    ];
                al[i][3] = As_lo[kc + q + 4][mb + r + 8];
            }
            #pragma unroll
            for (int j = 0; j < 8; ++j) {
                const int nb = n0w + j * 8 + r;
                uint32_t bh0 = Ws_hi[kc + q    ][nb];
                uint32_t bh1 = Ws_hi[kc + q + 4][nb];
                uint32_t bl0 = Ws_lo[kc + q    ][nb];
                uint32_t bl1 = Ws_lo[kc + q + 4][nb];
                #pragma unroll
                for (int i = 0; i < 2; ++i) {
                    mma_tf32(acc[i][j], ah[i][0], ah[i][1], ah[i][2], ah[i][3], bh0, bh1);
                    mma_tf32(acc[i][j], ah[i][0], ah[i][1], ah[i][2], ah[i][3], bl0, bl1);
                    mma_tf32(acc[i][j], al[i][0], al[i][1], al[i][2], al[i][3], bh0, bh1);
                }
            }
        }
        __syncthreads();
    }

    const int r = lane >> 2;
    const int q = lane & 3;
    #pragma unroll
    for (int i = 0; i < 2; ++i) {
        #pragma unroll
        for (int j = 0; j < 8; ++j) {
            const int row0 = m0 + m0w + i * 16 + r;
            const int col  = n0 + n0w + j * 8 + q * 2;
            float2 v0, v1;
            v0.x = acc[i][j][0]; v0.y = acc[i][j][1];
            v1.x = acc[i][j][2]; v1.y = acc[i][j][3];
            if (ACT == 1) {
                v0.x = siluf(v0.x); v0.y = siluf(v0.y);
                v1.x = siluf(v1.x); v1.y = siluf(v1.y);
            }
            *(float2*)&C[(size_t)row0       * N + col] = v0;
            *(float2*)&C[(size_t)(row0 + 8) * N + col] = v1;
        }
    }
}

__global__ __launch_bounds__(256) void gemm_qkv(
    const float* __restrict__ A,
    const float* __restrict__ Wq, const float* __restrict__ Wk,
    const float* __restrict__ Wv, int M, int N, int K)
{
    const float* W = (blockIdx.z == 0) ? Wq : (blockIdx.z == 1) ? Wk : Wv;
    float*       C = g_ptrs[blockIdx.z];
    gemm3t_core<1>(A, W, C, M, N, K);
}

__global__ __launch_bounds__(256) void gemm_out(
    const float* __restrict__ W, float* __restrict__ C, int M, int N, int K)
{
    const float* A = g_ptrs[5];
    gemm3t_core<0>(A, W, C, M, N, K);
}

// ---------------- beta = sigmoid(x @ Wbeta^T) --------------------------------
__global__ __launch_bounds__(128) void beta_gemv(
    const float* __restrict__ x, const float* __restrict__ Wb)
{
    float* beta = g_ptrs[3];
    const int row = blockIdx.x;
    __shared__ float xs[DM];
    const float4* xr = (const float4*)(x + (size_t)row * DM);
    float4* xs4 = (float4*)xs;
    xs4[threadIdx.x]       = xr[threadIdx.x];
    xs4[threadIdx.x + 128] = xr[threadIdx.x + 128];
    __syncthreads();

    const int j  = threadIdx.x >> 3;
    const int l8 = threadIdx.x & 7;
    const float* wr = Wb + (size_t)j * DM;
    float s = 0.f;
    for (int i = 0; i < DM/8; ++i) {
        int k = l8 + i*8;
        s += xs[k] * wr[k];
    }
    #pragma unroll
    for (int off = 4; off > 0; off >>= 1)
        s += __shfl_down_sync(0xffffffffu, s, off, 8);
    if (l8 == 0) beta[(size_t)row * NH + j] = sigmf(s);
}

// ---------------- per-head l2 normalize (in place) ---------------------------
__global__ __launch_bounds__(512) void l2norm_k()
{
    float* p = g_ptrs[blockIdx.y];   // 0 -> g_q, 1 -> g_k
    const int row  = blockIdx.x;
    const int w    = threadIdx.x >> 5;
    const int lane = threadIdx.x & 31;
    const size_t base = (size_t)row * DM + w * HD;
    float a = p[base + lane];
    float b = p[base + 32 + lane];
    float ss = a*a + b*b;
    #pragma unroll
    for (int off = 16; off > 0; off >>= 1)
        ss += __shfl_xor_sync(0xffffffffu, ss, off);
    float sc = 1.0f / (sqrtf(ss) + 1e-6f);
    p[base + lane]      = a * sc;
    p[base + 32 + lane] = b * sc;
}

// ---------------- small 64x64x64 smem GEMM micro-kernels ---------------------
// 256 threads, each owns a 4x4 output block. pitch = P65.
__device__ __forceinline__ void gemm_rr(
    const float* __restrict__ A, const float* __restrict__ B,
    float (&acc)[4][4], int i0, int j0)
{
    #pragma unroll 4
    for (int x = 0; x < 64; ++x) {
        float a0 = A[(i0+0)*P65+x], a1 = A[(i0+1)*P65+x];
        float a2 = A[(i0+2)*P65+x], a3 = A[(i0+3)*P65+x];
        float b0 = B[(j0+0)*P65+x], b1 = B[(j0+1)*P65+x];
        float b2 = B[(j0+2)*P65+x], b3 = B[(j0+3)*P65+x];
        acc[0][0]+=a0*b0; acc[0][1]+=a0*b1; acc[0][2]+=a0*b2; acc[0][3]+=a0*b3;
        acc[1][0]+=a1*b0; acc[1][1]+=a1*b1; acc[1][2]+=a1*b2; acc[1][3]+=a1*b3;
        acc[2][0]+=a2*b0; acc[2][1]+=a2*b1; acc[2][2]+=a2*b2; acc[2][3]+=a2*b3;
        acc[3][0]+=a3*b0; acc[3][1]+=a3*b1; acc[3][2]+=a3*b2; acc[3][3]+=a3*b3;
    }
}

__device__ __forceinline__ void gemm_rc(
    const float* __restrict__ A, const float* __restrict__ B,
    float (&acc)[4][4], int i0, int j0)
{
    #pragma unroll 4
    for (int x = 0; x < 64; ++x) {
        float a0 = A[(i0+0)*P65+x], a1 = A[(i0+1)*P65+x];
        float a2 = A[(i0+2)*P65+x], a3 = A[(i0+3)*P65+x];
        float b0 = B[x*P65+j0+0], b1 = B[x*P65+j0+1];
        float b2 = B[x*P65+j0+2], b3 = B[x*P65+j0+3];
        acc[0][0]+=a0*b0; acc[0][1]+=a0*b1; acc[0][2]+=a0*b2; acc[0][3]+=a0*b3;
        acc[1][0]+=a1*b0; acc[1][1]+=a1*b1; acc[1][2]+=a1*b2; acc[1][3]+=a1*b3;
        acc[2][0]+=a2*b0; acc[2][1]+=a2*b1; acc[2][2]+=a2*b2; acc[2][3]+=a2*b3;
        acc[3][0]+=a3*b0; acc[3][1]+=a3*b1; acc[3][2]+=a3*b2; acc[3][3]+=a3*b3;
    }
}

__device__ __forceinline__ void gemm_cc(
    const float* __restrict__ A, const float* __restrict__ B,
    float (&acc)[4][4], int i0, int j0)
{
    #pragma unroll 4
    for (int x = 0; x < 64; ++x) {
        float a0 = A[x*P65+i0+0], a1 = A[x*P65+i0+1];
        float a2 = A[x*P65+i0+2], a3 = A[x*P65+i0+3];
        float b0 = B[x*P65+j0+0], b1 = B[x*P65+j0+1];
        float b2 = B[x*P65+j0+2], b3 = B[x*P65+j0+3];
        acc[0][0]+=a0*b0; acc[0][1]+=a0*b1; acc[0][2]+=a0*b2; acc[0][3]+=a0*b3;
        acc[1][0]+=a1*b0; acc[1][1]+=a1*b1; acc[1][2]+=a1*b2; acc[1][3]+=a1*b3;
        acc[2][0]+=a2*b0; acc[2][1]+=a2*b1; acc[2][2]+=a2*b2; acc[2][3]+=a2*b3;
        acc[3][0]+=a3*b0; acc[3][1]+=a3*b1; acc[3][2]+=a3*b2; acc[3][3]+=a3*b3;
    }
}

// ---------------- chunk pre-kernel: A = K K^T, KV = K V^T --------------------
__global__ __launch_bounds__(256) void chunk_pre_k()
{
    __shared__ float sK[64*P65];
    __shared__ float sV[64*P65];

    const int ci    = blockIdx.x;
    const int chain = ci >> 5;       // /NCH
    const int c     = ci & 31;
    const int b     = chain >> 4;
    const int n     = chain & 15;
    const int tid   = threadIdx.x;
    const int i0    = (tid >> 4) << 2;
    const int j0    = (tid & 15) << 2;
    const size_t rbase = (size_t)(b*SS + c*CHUNK);

    for (int idx = tid; idx < 4096; idx += 256) {
        int t = idx >> 6, h = idx & 63;
        size_t g = (rbase + t) * DM + n*HD + h;
        sK[t*P65+h] = g_k[g];
        sV[t*P65+h] = g_v[g];
    }
    __syncthreads();

    float acc[4][4];
    zero44(acc);
    gemm_rr(sK, sK, acc, i0, j0);
    #pragma unroll
    for (int i = 0; i < 4; ++i)
        #pragma unroll
        for (int j = 0; j < 4; ++j)
            g_A[(size_t)ci*4096 + (i0+i)*64 + j0+j] = acc[i][j];

    zero44(acc);
    gemm_rr(sK, sV, acc, i0, j0);
    #pragma unroll
    for (int i = 0; i < 4; ++i)
        #pragma unroll
        for (int j = 0; j < 4; ++j)
            g_KV[(size_t)ci*4096 + (i0+i)*64 + j0+j] = acc[i][j];
}

// ---------------- serial core: per chain, loop chunks ------------------------
// 64 CTAs (one per chain), 256 threads. Per chunk:
//   T1 = K M^T;  R = KV - K T1^T;  solve G;  U = b(V - T1 - G K);  M += K^T U
__global__ __launch_bounds__(256) void delta_core_k()
{
    extern __shared__ float sm[];
    float* sM  = sm;               // state M[h][d]
    float* sK  = sM  + 64*P65;
    float* sVU = sK  + 64*P65;     // V then U
    float* sT1 = sVU + 64*P65;
    float* sR  = sT1 + 64*P65;     // KV then R
    float* sG  = sR  + 64*P65;
    float* sAm = sG  + 64*P65;     // A = KK^T
    float* sb  = sAm + 64*P65;     // beta[64]

    const int chain = blockIdx.x;
    const int b     = chain >> 4;
    const int n     = chain & 15;
    const int tid   = threadIdx.x;
    const int i0    = (tid >> 4) << 2;
    const int j0    = (tid & 15) << 2;
    const int tp    = tid >> 2;      // solve row
    const int sub   = tid & 3;

    for (int idx = tid; idx < 64*P65; idx += 256) sM[idx] = 0.f;
    __syncthreads();

    for (int c = 0; c < NCH; ++c) {
        const int ci = chain * NCH + c;
        const size_t rbase = (size_t)(b*SS + c*CHUNK);

        for (int idx = tid; idx < 4096; idx += 256) {
            int t = idx >> 6, h = idx & 63;
            size_t g = (rbase + t) * DM + n*HD + h;
            sK [t*P65+h] = g_k[g];
            sVU[t*P65+h] = g_v[g];
            sAm[t*P65+h] = g_A [(size_t)ci*4096 + idx];
            sR [t*P65+h] = g_KV[(size_t)ci*4096 + idx];
            sG [t*P65+h] = 0.f;
            g_M0[(size_t)ci*4096 + idx] = sM[t*P65+h];   // checkpoint (pre-update)
        }
        if (tid < 64) sb[tid] = g_beta[(rbase + tid)*NH + n];
        __syncthreads();

        // T1[t,h] = sum_d K[t,d] M[h,d]
        float acc[4][4];
        zero44(acc);
        gemm_rr(sK, sM, acc, i0, j0);
        #pragma unroll
        for (int i = 0; i < 4; ++i)
            #pragma unroll
            for (int j = 0; j < 4; ++j)
                sT1[(i0+i)*P65 + j0+j] = acc[i][j];
        __syncthreads();

        // R = KV - P, P[t',t] = sum_h K[t',h] T1[t,h]
        zero44(acc);
        gemm_rr(sK, sT1, acc, i0, j0);
        #pragma unroll
        for (int i = 0; i < 4; ++i)
            #pragma unroll
            for (int j = 0; j < 4; ++j)
                sR[(i0+i)*P65 + j0+j] -= acc[i][j];
        __syncthreads();

        // triangular solve: G[t',t] = b_t (R[t',t] - sum_{r<t} G[t,r] A[t',r])
        for (int t = 0; t < 64; ++t) {
            float s = 0.f;
            for (int r = sub; r < t; r += 4)
                s += sG[t*P65+r] * sAm[tp*P65+r];
            s += __shfl_down_sync(0xffffffffu, s, 2, 4);
            s += __shfl_down_sync(0xffffffffu, s, 1, 4);
            if (sub == 0 && tp > t)
                sG[tp*P65+t] = sb[t] * (sR[tp*P65+t] - s);
            __syncthreads();
        }

        // U = b*(V - T1 - G K);  (GK)[t,d] = sum_r G[t,r] K[r,d]
        zero44(acc);
        gemm_rc(sG, sK, acc, i0, j0);
        #pragma unroll
        for (int i = 0; i < 4; ++i) {
            #pragma unroll
            for (int j = 0; j < 4; ++j) {
                const int t = i0+i, d = j0+j;
                float u = sb[t] * (sVU[t*P65+d] - sT1[t*P65+d] - acc[i][j]);
                sVU[t*P65+d] = u;
                g_U[(size_t)ci*4096 + t*64 + d] = u;
            }
        }
        __syncthreads();

        // M[h,d] += sum_t K[t,h] U[t,d]
        zero44(acc);
        gemm_cc(sK, sVU, acc, i0, j0);
        #pragma unroll
        for (int i = 0; i < 4; ++i)
            #pragma unroll
            for (int j = 0; j < 4; ++j)
                sM[(i0+i)*P65 + j0+j] += acc[i][j];
        __syncthreads();
    }
}

// ---------------- epilogue: Out = Q M0 + tril(QK^T,-1) U  --------------------
__global__ __launch_bounds__(256) void delta_out_k()
{
    extern __shared__ float sm[];
    float* sQ  = sm;              // Q chunk
    float* sKQ = sQ  + 64*P65;    // K, then masked QK^T
    float* sM0 = sKQ + 64*P65;
    float* sU  = sM0 + 64*P65;

    const int ci    = blockIdx.x;
    const int chain = ci >> 5;
    const int c     = ci & 31;
    const int b     = chain >> 4;
    const int n     = chain & 15;
    const int tid   = threadIdx.x;
    const int i0    = (tid >> 4) << 2;
    const int j0    = (tid & 15) << 2;
    const size_t rbase = (size_t)(b*SS + c*CHUNK);

    for (int idx = tid; idx < 4096; idx += 256) {
        int t = idx >> 6, h = idx & 63;
        size_t g = (rbase + t) * DM + n*HD + h;
        sQ [t*P65+h] = g_q[g];
        sKQ[t*P65+h] = g_k[g];
        sM0[t*P65+h] = g_M0[(size_t)ci*4096 + idx];
        sU [t*P65+h] = g_U [(size_t)ci*4096 + idx];
    }
    __syncthreads();

    // QK[t,r] = sum_h Q[t,h] K[r,h]
    float acc[4][4];
    zero44(acc);
    gemm_rr(sQ, sKQ, acc, i0, j0);
    __syncthreads();   // all K reads done before overwrite
    #pragma unroll
    for (int i = 0; i < 4; ++i)
        #pragma unroll
        for (int j = 0; j < 4; ++j)
            sKQ[(i0+i)*P65 + j0+j] = (i0+i) > (j0+j) ? acc[i][j] : 0.f;
    __syncthreads();

    // Out[t,d] = sum_h Q[t,h] M0[h,d] + sum_r QK[t,r] U[r,d]
    zero44(acc);
    gemm_rc(sQ,  sM0, acc, i0, j0);
    gemm_rc(sKQ, sU,  acc, i0, j0);

    #pragma unroll
    for (int i = 0; i < 4; ++i)
        #pragma unroll
        for (int j = 0; j < 4; ++j)
            g_attn[(rbase + i0+i)*DM + n*HD + j0+j] = acc[i][j];
}

// ---------------- RMSNorm ----------------------------------------------------
__global__ __launch_bounds__(256) void rmsnorm_k(const float* __restrict__ w)
{
    const float* x = g_ptrs[4];
    float*       y = g_ptrs[5];
    const int row = blockIdx.x;
    const float4* xr = (const float4*)(x + (size_t)row * DM);
    float4 xv = xr[threadIdx.x];
    float ss = xv.x*xv.x + xv.y*xv.y + xv.z*xv.z + xv.w*xv.w;

    __shared__ float red[8];
    #pragma unroll
    for (int off = 16; off > 0; off >>= 1)
        ss += __shfl_xor_sync(0xffffffffu, ss, off);
    if ((threadIdx.x & 31) == 0) red[threadIdx.x >> 5] = ss;
    __syncthreads();
    float total = 0.f;
    #pragma unroll
    for (int i = 0; i < 8; ++i) total += red[i];

    const float inv = rsqrtf(total * (1.0f/DM) + 1e-6f);
    const float4* wr = (const float4*)w;
    float4 wv = wr[threadIdx.x];
    float4 o;
    o.x = xv.x * inv * wv.x;
    o.y = xv.y * inv * wv.y;
    o.z = xv.z * inv * wv.z;
    o.w = xv.w * inv * wv.w;
    ((float4*)(y + (size_t)row * DM))[threadIdx.x] = o;
}

// ---------------- launcher ---------------------------------------------------
extern "C" void kernel_launch(void* const* d_in, const int* in_sizes, int n_in,
                              void* d_out, int out_size)
{
    const float* x   = (const float*)d_in[0];
    const float* Wq  = (const float*)d_in[1];
    const float* Wk  = (const float*)d_in[2];
    const float* Wv  = (const float*)d_in[3];
    const float* Wo  = (const float*)d_in[4];
    const float* Wb  = (const float*)d_in[5];
    const float* rw  = (const float*)d_in[6];
    float* out = (float*)d_out;

    const int core_smem = (7*64*P65 + 64) * 4;   // ~116.7 KB
    const int epi_smem  = (4*64*P65) * 4;        // ~66.6 KB
    cudaFuncSetAttribute(delta_core_k, cudaFuncAttributeMaxDynamicSharedMemorySize, core_smem);
    cudaFuncSetAttribute(delta_out_k,  cudaFuncAttributeMaxDynamicSharedMemorySize, epi_smem);

    init_ptrs_k<<<1, 1>>>();

    dim3 gqkv(DM/128, ROWS/128, 3);
    gemm_qkv<<<gqkv, 256>>>(x, Wq, Wk, Wv, ROWS, DM, DM);
    beta_gemv<<<ROWS, 128>>>(x, Wb);

    dim3 gnorm(ROWS, 2);
    l2norm_k<<<gnorm, 512>>>();

    chunk_pre_k<<<NCI, 256>>>();
    delta_core_k<<<BB*NH, 256, core_smem>>>();
    delta_out_k<<<NCI, 256, epi_smem>>>();

    rmsnorm_k<<<ROWS, 256>>>(rw);

    dim3 go(DM/128, ROWS/128);
    gemm_out<<<go, 256>>>(Wo, out, ROWS, DM, DM);
}

// round 7
// speedup vs baseline: 1.5370x; 1.0606x over previous
#include <cuda_runtime.h>
#include <math.h>
#include <stdint.h>

#define DM   1024
#define NH   16
#define HD   64
#define BB   4
#define SS   2048
#define ROWS (BB*SS)   // 8192
#define CHUNK 64
#define NCH  (SS/CHUNK)       // 32 chunks per chain
#define NCI  (BB*NH*NCH)      // 2048 chunk instances
#define P65  65

#define WSZ  (DM*DM)          // 1M floats per weight
#define XSZ  (ROWS*DM)        // 8M floats

// ---------------- scratch (static device buffers; no allocation) ------------
__device__ float g_q[XSZ];
__device__ float g_k[XSZ];
__device__ float g_v[XSZ];
__device__ float g_beta[ROWS*NH];
__device__ float g_attn[XSZ];

// pre-split tf32 operands
__device__ float g_xhi[XSZ];
__device__ float g_xlo[XSZ];
__device__ float g_yhi[XSZ];
__device__ float g_ylo[XSZ];
__device__ float g_whi[4*WSZ];   // Wq,Wk,Wv,Wo
__device__ float g_wlo[4*WSZ];

// chunked delta-rule scratch
__device__ float g_A [NCI*4096];
__device__ float g_KV[NCI*4096];
__device__ float g_U [NCI*4096];
__device__ float g_M0[NCI*4096];

__device__ float* g_ptrs[4];

__global__ void init_ptrs_k()
{
    g_ptrs[0] = g_q;
    g_ptrs[1] = g_k;
    g_ptrs[2] = g_v;
    g_ptrs[3] = g_attn;
}

__device__ __forceinline__ float sigmf(float x){ return 1.0f/(1.0f+__expf(-x)); }
__device__ __forceinline__ float siluf(float x){ return x * sigmf(x); }

__device__ __forceinline__ void zero44(float (&acc)[4][4])
{
    #pragma unroll
    for (int i = 0; i < 4; ++i)
        #pragma unroll
        for (int j = 0; j < 4; ++j)
            acc[i][j] = 0.f;
}

// ---------------- tf32 helpers ----------------------------------------------
__device__ __forceinline__ float f2tf32f(float x)
{
    uint32_t r;
    asm("cvt.rna.tf32.f32 %0, %1;" : "=r"(r) : "f"(x));
    return __uint_as_float(r);
}

__device__ __forceinline__ void mma_tf32(float (&d)[4],
    float a0, float a1, float a2, float a3, float b0, float b1)
{
    asm volatile(
        "mma.sync.aligned.m16n8k8.row.col.f32.tf32.tf32.f32 "
        "{%0,%1,%2,%3}, {%4,%5,%6,%7}, {%8,%9}, {%0,%1,%2,%3};"
        : "+f"(d[0]), "+f"(d[1]), "+f"(d[2]), "+f"(d[3])
        : "r"(__float_as_uint(a0)), "r"(__float_as_uint(a1)),
          "r"(__float_as_uint(a2)), "r"(__float_as_uint(a3)),
          "r"(__float_as_uint(b0)), "r"(__float_as_uint(b1)));
}

__device__ __forceinline__ void cp16(uint32_t dst_smem, const void* src)
{
    asm volatile("cp.async.ca.shared.global [%0], [%1], 16;"
                 :: "r"(dst_smem), "l"(src));
}
__device__ __forceinline__ void cp_commit()
{
    asm volatile("cp.async.commit_group;");
}
template<int N> __device__ __forceinline__ void cp_wait()
{
    asm volatile("cp.async.wait_group %0;" :: "n"(N));
}

// ---------------- split x = hi + lo (tf32 each) ------------------------------
// z=0: x (XSZ); z=1..4: Wq/Wk/Wv/Wo (WSZ each)
__global__ __launch_bounds__(256) void split5_k(
    const float* __restrict__ x,
    const float* __restrict__ Wq, const float* __restrict__ Wk,
    const float* __restrict__ Wv, const float* __restrict__ Wo)
{
    const int z = blockIdx.z;
    const float* src; float* hi; float* lo; size_t n;
    if (z == 0)      { src = x;  hi = g_xhi;         lo = g_xlo;         n = XSZ; }
    else if (z == 1) { src = Wq; hi = g_whi;         lo = g_wlo;         n = WSZ; }
    else if (z == 2) { src = Wk; hi = g_whi + WSZ;   lo = g_wlo + WSZ;   n = WSZ; }
    else if (z == 3) { src = Wv; hi = g_whi + 2*WSZ; lo = g_wlo + 2*WSZ; n = WSZ; }
    else             { src = Wo; hi = g_whi + 3*WSZ; lo = g_wlo + 3*WSZ; n = WSZ; }

    size_t i4 = (size_t)blockIdx.x * 256 + threadIdx.x;
    if (i4 * 4 >= n) return;
    float4 v = ((const float4*)src)[i4];
    float4 h, l;
    h.x = f2tf32f(v.x); l.x = f2tf32f(v.x - h.x);
    h.y = f2tf32f(v.y); l.y = f2tf32f(v.y - h.y);
    h.z = f2tf32f(v.z); l.z = f2tf32f(v.z - h.z);
    h.w = f2tf32f(v.w); l.w = f2tf32f(v.w - h.w);
    ((float4*)hi)[i4] = h;
    ((float4*)lo)[i4] = l;
}

// ---------------- 3xTF32 GEMM v2: pre-split operands, cp.async 2-stage -------
// BM=BN=128, BK=16, 256 threads (8 warps), warp tile 32x64.
// smem per array per buffer: 128 rows x pitch 20 floats (16B aligned rows).
#define GP   20
#define GBUF (128*GP)          // 2560 floats
#define OFF_AH 0
#define OFF_AL (2*GBUF)
#define OFF_WH (4*GBUF)
#define OFF_WL (6*GBUF)
#define GSMEM  (8*GBUF*4)      // 81920 bytes

template<int ACT>
__device__ __forceinline__ void gemm3t_v2(
    const float* __restrict__ Ahi, const float* __restrict__ Alo,
    const float* __restrict__ Whi, const float* __restrict__ Wlo,
    float* __restrict__ C, int M, int N, int K)
{
    extern __shared__ float sm[];
    const uint32_t sbase = (uint32_t)__cvta_generic_to_shared(sm);

    const int tid  = threadIdx.x;
    const int lane = tid & 31;
    const int wid  = tid >> 5;
    const int m0   = blockIdx.y * 128;
    const int n0   = blockIdx.x * 128;
    const int m0w  = (wid >> 1) * 32;
    const int n0w  = (wid & 1)  * 64;
    const int rr   = lane >> 2;
    const int qq   = lane & 3;

    float acc[2][8][4];
    #pragma unroll
    for (int i = 0; i < 2; ++i)
        #pragma unroll
        for (int j = 0; j < 8; ++j)
            #pragma unroll
            for (int r = 0; r < 4; ++r) acc[i][j][r] = 0.f;

    // issue one K-tile's loads into buffer b
    auto issue = [&](int b, int kt) {
        const int k0 = kt * 16;
        #pragma unroll
        for (int cc = 0; cc < 2; ++cc) {
            const int c   = tid + cc * 256;   // 0..511
            const int row = c >> 2;
            const int q4  = (c & 3) * 4;
            const uint32_t soff = (uint32_t)((b*GBUF + row*GP + q4) * 4);
            const size_t ga = (size_t)(m0 + row) * K + k0 + q4;
            const size_t gw = (size_t)(n0 + row) * K + k0 + q4;
            cp16(sbase + OFF_AH*4 + soff, Ahi + ga);
            cp16(sbase + OFF_AL*4 + soff, Alo + ga);
            cp16(sbase + OFF_WH*4 + soff, Whi + gw);
            cp16(sbase + OFF_WL*4 + soff, Wlo + gw);
        }
    };

    const int NT = K / 16;
    issue(0, 0);
    cp_commit();

    for (int kt = 0; kt < NT; ++kt) {
        const int cur = kt & 1;
        if (kt + 1 < NT) {
            issue(cur ^ 1, kt + 1);
            cp_commit();
            cp_wait<1>();
        } else {
            cp_wait<0>();
        }
        __syncthreads();

        const float* sAh = sm + OFF_AH + cur*GBUF;
        const float* sAl = sm + OFF_AL + cur*GBUF;
        const float* sWh = sm + OFF_WH + cur*GBUF;
        const float* sWl = sm + OFF_WL + cur*GBUF;

        #pragma unroll
        for (int c = 0; c < 2; ++c) {
            const int kc = c * 8;
            float ah[2][4], al[2][4];
            #pragma unroll
            for (int i = 0; i < 2; ++i) {
                const int mb = m0w + i * 16;
                ah[i][0] = sAh[(mb+rr  )*GP + kc+qq  ];
                ah[i][1] = sAh[(mb+rr+8)*GP + kc+qq  ];
                ah[i][2] = sAh[(mb+rr  )*GP + kc+qq+4];
                ah[i][3] = sAh[(mb+rr+8)*GP + kc+qq+4];
                al[i][0] = sAl[(mb+rr  )*GP + kc+qq  ];
                al[i][1] = sAl[(mb+rr+8)*GP + kc+qq  ];
                al[i][2] = sAl[(mb+rr  )*GP + kc+qq+4];
                al[i][3] = sAl[(mb+rr+8)*GP + kc+qq+4];
            }
            #pragma unroll
            for (int j = 0; j < 8; ++j) {
                const int nb = n0w + j * 8 + rr;
                float bh0 = sWh[nb*GP + kc+qq  ];
                float bh1 = sWh[nb*GP + kc+qq+4];
                float bl0 = sWl[nb*GP + kc+qq  ];
                float bl1 = sWl[nb*GP + kc+qq+4];
                #pragma unroll
                for (int i = 0; i < 2; ++i) {
                    mma_tf32(acc[i][j], ah[i][0], ah[i][1], ah[i][2], ah[i][3], bh0, bh1);
                    mma_tf32(acc[i][j], ah[i][0], ah[i][1], ah[i][2], ah[i][3], bl0, bl1);
                    mma_tf32(acc[i][j], al[i][0], al[i][1], al[i][2], al[i][3], bh0, bh1);
                }
            }
        }
        __syncthreads();
    }

    #pragma unroll
    for (int i = 0; i < 2; ++i) {
        #pragma unroll
        for (int j = 0; j < 8; ++j) {
            const int row0 = m0 + m0w + i * 16 + rr;
            const int col  = n0 + n0w + j * 8 + qq * 2;
            float2 v0, v1;
            v0.x = acc[i][j][0]; v0.y = acc[i][j][1];
            v1.x = acc[i][j][2]; v1.y = acc[i][j][3];
            if (ACT == 1) {
                v0.x = siluf(v0.x); v0.y = siluf(v0.y);
                v1.x = siluf(v1.x); v1.y = siluf(v1.y);
            }
            *(float2*)&C[(size_t)row0       * N + col] = v0;
            *(float2*)&C[(size_t)(row0 + 8) * N + col] = v1;
        }
    }
}

__global__ __launch_bounds__(256, 2) void gemm_qkv(int M, int N, int K)
{
    const int z = blockIdx.z;
    gemm3t_v2<1>(g_xhi, g_xlo, g_whi + (size_t)z*WSZ, g_wlo + (size_t)z*WSZ,
                 g_ptrs[z], M, N, K);
}

__global__ __launch_bounds__(256, 2) void gemm_out(float* __restrict__ C,
                                                   int M, int N, int K)
{
    gemm3t_v2<0>(g_yhi, g_ylo, g_whi + 3*(size_t)WSZ, g_wlo + 3*(size_t)WSZ,
                 C, M, N, K);
}

// ---------------- beta = sigmoid(x @ Wbeta^T) --------------------------------
__global__ __launch_bounds__(128) void beta_gemv(
    const float* __restrict__ x, const float* __restrict__ Wb)
{
    const int row = blockIdx.x;
    __shared__ float xs[DM];
    const float4* xr = (const float4*)(x + (size_t)row * DM);
    float4* xs4 = (float4*)xs;
    xs4[threadIdx.x]       = xr[threadIdx.x];
    xs4[threadIdx.x + 128] = xr[threadIdx.x + 128];
    __syncthreads();

    const int j  = threadIdx.x >> 3;
    const int l8 = threadIdx.x & 7;
    const float* wr = Wb + (size_t)j * DM;
    float s = 0.f;
    for (int i = 0; i < DM/8; ++i) {
        int k = l8 + i*8;
        s += xs[k] * wr[k];
    }
    #pragma unroll
    for (int off = 4; off > 0; off >>= 1)
        s += __shfl_down_sync(0xffffffffu, s, off, 8);
    if (l8 == 0) g_beta[(size_t)row * NH + j] = sigmf(s);
}

// ---------------- per-head l2 normalize (in place) ---------------------------
__global__ __launch_bounds__(512) void l2norm_k()
{
    float* p = g_ptrs[blockIdx.y];   // 0 -> g_q, 1 -> g_k
    const int row  = blockIdx.x;
    const int w    = threadIdx.x >> 5;
    const int lane = threadIdx.x & 31;
    const size_t base = (size_t)row * DM + w * HD;
    float a = p[base + lane];
    float b = p[base + 32 + lane];
    float ss = a*a + b*b;
    #pragma unroll
    for (int off = 16; off > 0; off >>= 1)
        ss += __shfl_xor_sync(0xffffffffu, ss, off);
    float sc = 1.0f / (sqrtf(ss) + 1e-6f);
    p[base + lane]      = a * sc;
    p[base + 32 + lane] = b * sc;
}

// ---------------- small 64x64x64 smem GEMM micro-kernels ---------------------
__device__ __forceinline__ void gemm_rr(
    const float* __restrict__ A, const float* __restrict__ B,
    float (&acc)[4][4], int i0, int j0)
{
    #pragma unroll 4
    for (int x = 0; x < 64; ++x) {
        float a0 = A[(i0+0)*P65+x], a1 = A[(i0+1)*P65+x];
        float a2 = A[(i0+2)*P65+x], a3 = A[(i0+3)*P65+x];
        float b0 = B[(j0+0)*P65+x], b1 = B[(j0+1)*P65+x];
        float b2 = B[(j0+2)*P65+x], b3 = B[(j0+3)*P65+x];
        acc[0][0]+=a0*b0; acc[0][1]+=a0*b1; acc[0][2]+=a0*b2; acc[0][3]+=a0*b3;
        acc[1][0]+=a1*b0; acc[1][1]+=a1*b1; acc[1][2]+=a1*b2; acc[1][3]+=a1*b3;
        acc[2][0]+=a2*b0; acc[2][1]+=a2*b1; acc[2][2]+=a2*b2; acc[2][3]+=a2*b3;
        acc[3][0]+=a3*b0; acc[3][1]+=a3*b1; acc[3][2]+=a3*b2; acc[3][3]+=a3*b3;
    }
}

__device__ __forceinline__ void gemm_rc(
    const float* __restrict__ A, const float* __restrict__ B,
    float (&acc)[4][4], int i0, int j0)
{
    #pragma unroll 4
    for (int x = 0; x < 64; ++x) {
        float a0 = A[(i0+0)*P65+x], a1 = A[(i0+1)*P65+x];
        float a2 = A[(i0+2)*P65+x], a3 = A[(i0+3)*P65+x];
        float b0 = B[x*P65+j0+0], b1 = B[x*P65+j0+1];
        float b2 = B[x*P65+j0+2], b3 = B[x*P65+j0+3];
        acc[0][0]+=a0*b0; acc[0][1]+=a0*b1; acc[0][2]+=a0*b2; acc[0][3]+=a0*b3;
        acc[1][0]+=a1*b0; acc[1][1]+=a1*b1; acc[1][2]+=a1*b2; acc[1][3]+=a1*b3;
        acc[2][0]+=a2*b0; acc[2][1]+=a2*b1; acc[2][2]+=a2*b2; acc[2][3]+=a2*b3;
        acc[3][0]+=a3*b0; acc[3][1]+=a3*b1; acc[3][2]+=a3*b2; acc[3][3]+=a3*b3;
    }
}

__device__ __forceinline__ void gemm_cc(
    const float* __restrict__ A, const float* __restrict__ B,
    float (&acc)[4][4], int i0, int j0)
{
    #pragma unroll 4
    for (int x = 0; x < 64; ++x) {
        float a0 = A[x*P65+i0+0], a1 = A[x*P65+i0+1];
        float a2 = A[x*P65+i0+2], a3 = A[x*P65+i0+3];
        float b0 = B[x*P65+j0+0], b1 = B[x*P65+j0+1];
        float b2 = B[x*P65+j0+2], b3 = B[x*P65+j0+3];
        acc[0][0]+=a0*b0; acc[0][1]+=a0*b1; acc[0][2]+=a0*b2; acc[0][3]+=a0*b3;
        acc[1][0]+=a1*b0; acc[1][1]+=a1*b1; acc[1][2]+=a1*b2; acc[1][3]+=a1*b3;
        acc[2][0]+=a2*b0; acc[2][1]+=a2*b1; acc[2][2]+=a2*b2; acc[2][3]+=a2*b3;
        acc[3][0]+=a3*b0; acc[3][1]+=a3*b1; acc[3][2]+=a3*b2; acc[3][3]+=a3*b3;
    }
}

// ---------------- chunk pre-kernel: A = K K^T, KV = K V^T --------------------
__global__ __launch_bounds__(256) void chunk_pre_k()
{
    __shared__ float sK[64*P65];
    __shared__ float sV[64*P65];

    const int ci    = blockIdx.x;
    const int chain = ci >> 5;
    const int c     = ci & 31;
    const int b     = chain >> 4;
    const int n     = chain & 15;
    const int tid   = threadIdx.x;
    const int i0    = (tid >> 4) << 2;
    const int j0    = (tid & 15) << 2;
    const size_t rbase = (size_t)(b*SS + c*CHUNK);

    for (int idx = tid; idx < 4096; idx += 256) {
        int t = idx >> 6, h = idx & 63;
        size_t g = (rbase + t) * DM + n*HD + h;
        sK[t*P65+h] = g_k[g];
        sV[t*P65+h] = g_v[g];
    }
    __syncthreads();

    float acc[4][4];
    zero44(acc);
    gemm_rr(sK, sK, acc, i0, j0);
    #pragma unroll
    for (int i = 0; i < 4; ++i)
        #pragma unroll
        for (int j = 0; j < 4; ++j)
            g_A[(size_t)ci*4096 + (i0+i)*64 + j0+j] = acc[i][j];

    zero44(acc);
    gemm_rr(sK, sV, acc, i0, j0);
    #pragma unroll
    for (int i = 0; i < 4; ++i)
        #pragma unroll
        for (int j = 0; j < 4; ++j)
            g_KV[(size_t)ci*4096 + (i0+i)*64 + j0+j] = acc[i][j];
}

// ---------------- serial core: per chain, loop chunks ------------------------
__global__ __launch_bounds__(256) void delta_core_k()
{
    extern __shared__ float smc[];
    float* sM  = smc;
    float* sK  = sM  + 64*P65;
    float* sVU = sK  + 64*P65;
    float* sT1 = sVU + 64*P65;
    float* sR  = sT1 + 64*P65;
    float* sG  = sR  + 64*P65;
    float* sAm = sG  + 64*P65;
    float* sb  = sAm + 64*P65;

    const int chain = blockIdx.x;
    const int b     = chain >> 4;
    const int n     = chain & 15;
    const int tid   = threadIdx.x;
    const int i0    = (tid >> 4) << 2;
    const int j0    = (tid & 15) << 2;
    const int tp    = tid >> 2;
    const int sub   = tid & 3;

    for (int idx = tid; idx < 64*P65; idx += 256) sM[idx] = 0.f;
    __syncthreads();

    for (int c = 0; c < NCH; ++c) {
        const int ci = chain * NCH + c;
        const size_t rbase = (size_t)(b*SS + c*CHUNK);

        for (int idx = tid; idx < 4096; idx += 256) {
            int t = idx >> 6, h = idx & 63;
            size_t g = (rbase + t) * DM + n*HD + h;
            sK [t*P65+h] = g_k[g];
            sVU[t*P65+h] = g_v[g];
            sAm[t*P65+h] = g_A [(size_t)ci*4096 + idx];
            sR [t*P65+h] = g_KV[(size_t)ci*4096 + idx];
            sG [t*P65+h] = 0.f;
            g_M0[(size_t)ci*4096 + idx] = sM[t*P65+h];
        }
        if (tid < 64) sb[tid] = g_beta[(rbase + tid)*NH + n];
        __syncthreads();

        float acc[4][4];
        zero44(acc);
        gemm_rr(sK, sM, acc, i0, j0);
        #pragma unroll
        for (int i = 0; i < 4; ++i)
            #pragma unroll
            for (int j = 0; j < 4; ++j)
                sT1[(i0+i)*P65 + j0+j] = acc[i][j];
        __syncthreads();

        zero44(acc);
        gemm_rr(sK, sT1, acc, i0, j0);
        #pragma unroll
        for (int i = 0; i < 4; ++i)
            #pragma unroll
            for (int j = 0; j < 4; ++j)
                sR[(i0+i)*P65 + j0+j] -= acc[i][j];
        __syncthreads();

        for (int t = 0; t < 64; ++t) {
            float s = 0.f;
            for (int r = sub; r < t; r += 4)
                s += sG[t*P65+r] * sAm[tp*P65+r];
            s += __shfl_down_sync(0xffffffffu, s, 2, 4);
            s += __shfl_down_sync(0xffffffffu, s, 1, 4);
            if (sub == 0 && tp > t)
                sG[tp*P65+t] = sb[t] * (sR[tp*P65+t] - s);
            __syncthreads();
        }

        zero44(acc);
        gemm_rc(sG, sK, acc, i0, j0);
        #pragma unroll
        for (int i = 0; i < 4; ++i) {
            #pragma unroll
            for (int j = 0; j < 4; ++j) {
                const int t = i0+i, d = j0+j;
                float u = sb[t] * (sVU[t*P65+d] - sT1[t*P65+d] - acc[i][j]);
                sVU[t*P65+d] = u;
                g_U[(size_t)ci*4096 + t*64 + d] = u;
            }
        }
        __syncthreads();

        zero44(acc);
        gemm_cc(sK, sVU, acc, i0, j0);
        #pragma unroll
        for (int i = 0; i < 4; ++i)
            #pragma unroll
            for (int j = 0; j < 4; ++j)
                sM[(i0+i)*P65 + j0+j] += acc[i][j];
        __syncthreads();
    }
}

// ---------------- epilogue: Out = Q M0 + tril(QK^T,-1) U  --------------------
__global__ __launch_bounds__(256) void delta_out_k()
{
    extern __shared__ float smo[];
    float* sQ  = smo;
    float* sKQ = sQ  + 64*P65;
    float* sM0 = sKQ + 64*P65;
    float* sU  = sM0 + 64*P65;

    const int ci    = blockIdx.x;
    const int chain = ci >> 5;
    const int c     = ci & 31;
    const int b     = chain >> 4;
    const int n     = chain & 15;
    const int tid   = threadIdx.x;
    const int i0    = (tid >> 4) << 2;
    const int j0    = (tid & 15) << 2;
    const size_t rbase = (size_t)(b*SS + c*CHUNK);

    for (int idx = tid; idx < 4096; idx += 256) {
        int t = idx >> 6, h = idx & 63;
        size_t g = (rbase + t) * DM + n*HD + h;
        sQ [t*P65+h] = g_q[g];
        sKQ[t*P65+h] = g_k[g];
        sM0[t*P65+h] = g_M0[(size_t)ci*4096 + idx];
        sU [t*P65+h] = g_U [(size_t)ci*4096 + idx];
    }
    __syncthreads();

    float acc[4][4];
    zero44(acc);
    gemm_rr(sQ, sKQ, acc, i0, j0);
    __syncthreads();
    #pragma unroll
    for (int i = 0; i < 4; ++i)
        #pragma unroll
        for (int j = 0; j < 4; ++j)
            sKQ[(i0+i)*P65 + j0+j] = (i0+i) > (j0+j) ? acc[i][j] : 0.f;
    __syncthreads();

    zero44(acc);
    gemm_rc(sQ,  sM0, acc, i0, j0);
    gemm_rc(sKQ, sU,  acc, i0, j0);

    #pragma unroll
    for (int i = 0; i < 4; ++i)
        #pragma unroll
        for (int j = 0; j < 4; ++j)
            g_attn[(rbase + i0+i)*DM + n*HD + j0+j] = acc[i][j];
}

// ---------------- RMSNorm (fused tf32 split of y) ----------------------------
__global__ __launch_bounds__(256) void rmsnorm_k(const float* __restrict__ w)
{
    const float* x = g_attn;
    const int row = blockIdx.x;
    const float4* xr = (const float4*)(x + (size_t)row * DM);
    float4 xv = xr[threadIdx.x];
    float ss = xv.x*xv.x + xv.y*xv.y + xv.z*xv.z + xv.w*xv.w;

    __shared__ float red[8];
    #pragma unroll
    for (int off = 16; off > 0; off >>= 1)
        ss += __shfl_xor_sync(0xffffffffu, ss, off);
    if ((threadIdx.x & 31) == 0) red[threadIdx.x >> 5] = ss;
    __syncthreads();
    float total = 0.f;
    #pragma unroll
    for (int i = 0; i < 8; ++i) total += red[i];

    const float inv = rsqrtf(total * (1.0f/DM) + 1e-6f);
    const float4* wr = (const float4*)w;
    float4 wv = wr[threadIdx.x];
    float4 o, h, l;
    o.x = xv.x * inv * wv.x; h.x = f2tf32f(o.x); l.x = f2tf32f(o.x - h.x);
    o.y = xv.y * inv * wv.y; h.y = f2tf32f(o.y); l.y = f2tf32f(o.y - h.y);
    o.z = xv.z * inv * wv.z; h.z = f2tf32f(o.z); l.z = f2tf32f(o.z - h.z);
    o.w = xv.w * inv * wv.w; h.w = f2tf32f(o.w); l.w = f2tf32f(o.w - h.w);
    ((float4*)(g_yhi + (size_t)row * DM))[threadIdx.x] = h;
    ((float4*)(g_ylo + (size_t)row * DM))[threadIdx.x] = l;
}

// ---------------- launcher ---------------------------------------------------
extern "C" void kernel_launch(void* const* d_in, const int* in_sizes, int n_in,
                              void* d_out, int out_size)
{
    const float* x   = (const float*)d_in[0];
    const float* Wq  = (const float*)d_in[1];
    const float* Wk  = (const float*)d_in[2];
    const float* Wv  = (const float*)d_in[3];
    const float* Wo  = (const float*)d_in[4];
    const float* Wb  = (const float*)d_in[5];
    const float* rw  = (const float*)d_in[6];
    float* out = (float*)d_out;

    const int core_smem = (7*64*P65 + 64) * 4;
    const int epi_smem  = (4*64*P65) * 4;
    cudaFuncSetAttribute(delta_core_k, cudaFuncAttributeMaxDynamicSharedMemorySize, core_smem);
    cudaFuncSetAttribute(delta_out_k,  cudaFuncAttributeMaxDynamicSharedMemorySize, epi_smem);
    cudaFuncSetAttribute(gemm_qkv, cudaFuncAttributeMaxDynamicSharedMemorySize, GSMEM);
    cudaFuncSetAttribute(gemm_out, cudaFuncAttributeMaxDynamicSharedMemorySize, GSMEM);

    init_ptrs_k<<<1, 1>>>();                             // 1

    dim3 gsplit(XSZ/4/256, 1, 5);
    split5_k<<<gsplit, 256>>>(x, Wq, Wk, Wv, Wo);        // 2

    beta_gemv<<<ROWS, 128>>>(x, Wb);                     // 3

    dim3 gqkv(DM/128, ROWS/128, 3);
    gemm_qkv<<<gqkv, 256, GSMEM>>>(ROWS, DM, DM);        // 4  <- profile slot

    dim3 gnorm(ROWS, 2);
    l2norm_k<<<gnorm, 512>>>();                          // 5

    chunk_pre_k<<<NCI, 256>>>();                         // 6
    delta_core_k<<<BB*NH, 256, core_smem>>>();           // 7
    delta_out_k<<<NCI, 256, epi_smem>>>();               // 8

    rmsnorm_k<<<ROWS, 256>>>(rw);                        // 9

    dim3 go(DM/128, ROWS/128);
    gemm_out<<<go, 256, GSMEM>>>(out, ROWS, DM, DM);     // 10
}